// round 14
// baseline (speedup 1.0000x reference)
#include <cuda_runtime.h>
#include <cuda_fp16.h>
#include <cstdint>

#define NB 8
#define CC 64
#define DH 32
#define NN 4096
#define LOG2E 1.4426950408889634f

// fp16 staging buffers (device globals; no allocation allowed)
__device__ __half g_Q[NB * NN * DH];   // [B][N][32]
__device__ __half g_K[NB * NN * DH];   // [B][N][32] (pre-scaled by log2e)
__device__ __half g_V[NB * NN * CC];   // [B][N][64]

// ---------------------------------------------------------------------------
static __device__ __forceinline__ uint32_t cvta_s(const void* p) {
    return (uint32_t)__cvta_generic_to_shared(p);
}
static __device__ __forceinline__ uint32_t packh(float lo, float hi) {
    uint32_t r;
    asm("cvt.rn.f16x2.f32 %0, %1, %2;" : "=r"(r) : "f"(hi), "f"(lo));
    return r;
}
static __device__ __forceinline__ uint32_t ex2h2(uint32_t x) {
    uint32_t r;
    asm("ex2.approx.f16x2 %0, %1;" : "=r"(r) : "r"(x));
    return r;
}
static __device__ __forceinline__ unsigned long long pk2(float lo, float hi) {
    unsigned long long d;
    asm("mov.b64 %0, {%1,%2};" : "=l"(d) : "f"(lo), "f"(hi));
    return d;
}
static __device__ __forceinline__ void upk2(float& lo, float& hi, unsigned long long d) {
    asm("mov.b64 {%0,%1}, %2;" : "=f"(lo), "=f"(hi) : "l"(d));
}
static __device__ __forceinline__ unsigned long long fma2(
    unsigned long long a, unsigned long long b, unsigned long long c) {
    unsigned long long d;
    asm("fma.rn.f32x2 %0, %1, %2, %3;" : "=l"(d) : "l"(a), "l"(b), "l"(c));
    return d;
}
static __device__ __forceinline__ void ldsm4(uint32_t* r, uint32_t a) {
    asm volatile("ldmatrix.sync.aligned.m8n8.x4.shared.b16 {%0,%1,%2,%3},[%4];"
        : "=r"(r[0]), "=r"(r[1]), "=r"(r[2]), "=r"(r[3]) : "r"(a));
}
static __device__ __forceinline__ void ldsm4t(uint32_t* r, uint32_t a) {
    asm volatile("ldmatrix.sync.aligned.m8n8.x4.trans.shared.b16 {%0,%1,%2,%3},[%4];"
        : "=r"(r[0]), "=r"(r[1]), "=r"(r[2]), "=r"(r[3]) : "r"(a));
}
static __device__ __forceinline__ void ldsm2t(uint32_t* r, uint32_t a) {
    asm volatile("ldmatrix.sync.aligned.m8n8.x2.trans.shared.b16 {%0,%1},[%2];"
        : "=r"(r[0]), "=r"(r[1]) : "r"(a));
}
// f16 x f16 -> f16 accum
static __device__ __forceinline__ void mmah(uint32_t* d, const uint32_t* a,
                                            uint32_t b0, uint32_t b1) {
    asm volatile("mma.sync.aligned.m16n8k16.row.col.f16.f16.f16.f16 "
        "{%0,%1},{%2,%3,%4,%5},{%6,%7},{%0,%1};"
        : "+r"(d[0]), "+r"(d[1])
        : "r"(a[0]), "r"(a[1]), "r"(a[2]), "r"(a[3]), "r"(b0), "r"(b1));
}
// f16 x f16 -> f32 accum
static __device__ __forceinline__ void mmaf(float* d, const uint32_t* a,
                                            uint32_t b0, uint32_t b1) {
    asm volatile("mma.sync.aligned.m16n8k16.row.col.f32.f16.f16.f32 "
        "{%0,%1,%2,%3},{%4,%5,%6,%7},{%8,%9},{%0,%1,%2,%3};"
        : "+f"(d[0]), "+f"(d[1]), "+f"(d[2]), "+f"(d[3])
        : "r"(a[0]), "r"(a[1]), "r"(a[2]), "r"(a[3]), "r"(b0), "r"(b1));
}
static __device__ __forceinline__ void cpasync16(uint32_t dst, const void* src) {
    asm volatile("cp.async.cg.shared.global [%0],[%1],16;" :: "r"(dst), "l"(src));
}

// ---------------------------------------------------------------------------
// Projection on tensor cores — 256 threads, 8 warps x 16 n-rows (R13).
// ---------------------------------------------------------------------------
#define WS_OFF 0        // W f16 [128][72]   (18432 B)
#define XS_OFF 18432    // x f16 [64][136]   (17408 B)
#define SB_OFF 35840    // bias f32 [128]    (512 B)
#define OS_OFF 36352    // out f16 [128][136] (34816 B)
#define PROJ_SMEM 71168

__global__ __launch_bounds__(256) void proj_kernel(
    const float* __restrict__ x,
    const float* __restrict__ wq, const float* __restrict__ bq,
    const float* __restrict__ wk, const float* __restrict__ bk,
    const float* __restrict__ wv, const float* __restrict__ bv)
{
    extern __shared__ char psm[];
    const uint32_t smB = cvta_s(psm);
    const int tid = threadIdx.x;
    const int wid = tid >> 5, L = tid & 31;
    const int g = L >> 2, tig = L & 3;
    const int b  = blockIdx.x >> 5;
    const int n0 = (blockIdx.x & 31) << 7;

    float* sb = (float*)(psm + SB_OFF);
    if (tid < 128) {
        float v = (tid < 32) ? bq[tid]
                : (tid < 64) ? bk[tid - 32] * LOG2E
                             : bv[tid - 64];
        sb[tid] = v;
    }
    for (int u = tid; u < 2048; u += 256) {
        int dim = u >> 4, c = (u & 15) << 2;
        float4 w;
        if (dim < 32)      w = *(const float4*)&wq[(dim << 6) + c];
        else if (dim < 64) {
            w = *(const float4*)&wk[((dim - 32) << 6) + c];
            w.x *= LOG2E; w.y *= LOG2E; w.z *= LOG2E; w.w *= LOG2E;
        } else             w = *(const float4*)&wv[((dim - 64) << 6) + c];
        *(uint2*)(psm + WS_OFF + dim * 144 + c * 2) =
            make_uint2(packh(w.x, w.y), packh(w.z, w.w));
    }
    for (int u = tid; u < 2048; u += 256) {
        int c = u >> 5, sg = u & 31;
        float4 xa = *(const float4*)&x[((((b << 6) + c) << 12)) + n0 + (sg << 2)];
        *(uint2*)(psm + XS_OFF + c * 272 + sg * 8) =
            make_uint2(packh(xa.x, xa.y), packh(xa.z, xa.w));
    }
    __syncthreads();

    const int mbase = wid << 4;
    uint32_t af[4][4];
    const uint32_t aRow = (L & 7) + ((L >> 4) << 3);
    const uint32_t aCol = ((L >> 3) & 1) << 4;
#pragma unroll
    for (int ks = 0; ks < 4; ks++)
        ldsm4t(af[ks], smB + XS_OFF + (ks * 16 + aRow) * 272 + mbase * 2 + aCol);

    const uint32_t wRow = L & 7;
    const uint32_t wCol = ((L >> 3) & 3) << 4;
#pragma unroll
    for (int nt = 0; nt < 16; nt++) {
        float d[4];
        float2 bias = *(float2*)&sb[nt * 8 + 2 * tig];
        d[0] = bias.x; d[1] = bias.y; d[2] = bias.x; d[3] = bias.y;
        uint32_t w0[4], w1[4];
        ldsm4(w0, smB + WS_OFF + (nt * 8 + wRow) * 144 + wCol);
        ldsm4(w1, smB + WS_OFF + (nt * 8 + wRow) * 144 + 64 + wCol);
        mmaf(d, af[0], w0[0], w0[1]);
        mmaf(d, af[1], w0[2], w0[3]);
        mmaf(d, af[2], w1[0], w1[1]);
        mmaf(d, af[3], w1[2], w1[3]);
        *(uint32_t*)(psm + OS_OFF + (mbase + g) * 272 + nt * 16 + tig * 4)
            = packh(d[0], d[1]);
        *(uint32_t*)(psm + OS_OFF + (mbase + g + 8) * 272 + nt * 16 + tig * 4)
            = packh(d[2], d[3]);
    }
    __syncthreads();

    for (int u = tid; u < 2048; u += 256) {
        int n = u >> 4, seg = u & 15;
        uint4 v = *(uint4*)(psm + OS_OFF + n * 272 + seg * 16);
        int gn = (b << 12) + n0 + n;
        if (seg < 4)      *(uint4*)&g_Q[(gn << 5) + seg * 8] = v;
        else if (seg < 8) *(uint4*)&g_K[(gn << 5) + (seg - 4) * 8] = v;
        else              *(uint4*)&g_V[(gn << 6) + (seg - 8) * 8] = v;
    }
}

// ---------------------------------------------------------------------------
// Flash attention: R13 core + 3-stage cp.async pipeline (depth-2 prefetch,
// ONE __syncthreads per 128-key tile).
// ---------------------------------------------------------------------------
#define QS_OFF  0
#define KS_OFF  14336           // 3 x 14336 -> ends 57344
#define VS_OFF  57344           // 3 x 18432 -> ends 112640
#define K_BUF   14336
#define V_BUF   18432
#define SMEM_ATTN 112640
#define SHIFT2  0xC800C800u     // f16x2 {-8, -8}

__global__ __launch_bounds__(128, 2) void attn_kernel(
    const float* __restrict__ wz, const float* __restrict__ bz,
    const float* __restrict__ hin, float* __restrict__ outp)
{
    extern __shared__ char sm8[];
    __half* Qs = (__half*)(sm8 + QS_OFF);
    float* zs  = (float*)sm8;                 // epilogue overlay (33792 B)
    float* wzs = (float*)(sm8 + 33792);       // (17408 B)

    const int tid = threadIdx.x;
    const int wid = tid >> 5, L = tid & 31;
    const int g = L >> 2, tig = L & 3;
    const int b  = blockIdx.x >> 5;
    const int n0 = (blockIdx.x & 31) << 7;
    const int m0w = wid << 5;

    const uint32_t qsB = cvta_s(sm8 + QS_OFF);
    const uint32_t ksB = cvta_s(sm8 + KS_OFF);
    const uint32_t vsB = cvta_s(sm8 + VS_OFF);

    // ones-column (cols 64..71) of every V row, all 3 buffers
    for (int t = tid; t < 384; t += 128) {
        int buf = t >> 7, row = t & 127;
        *(uint4*)(sm8 + VS_OFF + buf * V_BUF + row * 144 + 128) =
            make_uint4(0x00003C00u, 0u, 0u, 0u);
    }

    // --- prologue: issue tiles 0 and 1, stage Q ---
#pragma unroll
    for (int it = 0; it < 2; it++) {
        const int r0g = it << 7;
        for (int u = tid; u < 512; u += 128) {
            int row = u >> 2, seg = u & 3;
            cpasync16(ksB + it * K_BUF + row * 112 + seg * 16,
                      &g_K[(((b << 12) + r0g + row) << 5) + seg * 8]);
        }
        for (int u = tid; u < 1024; u += 128) {
            int vr = u >> 3, vs = u & 7;
            cpasync16(vsB + it * V_BUF + vr * 144 + vs * 16,
                      &g_V[(((b << 12) + r0g + vr) << 6) + vs * 8]);
        }
        asm volatile("cp.async.commit_group;");
    }
    for (int t = tid; t < 512; t += 128) {
        int row = t >> 2, seg = t & 3;
        *(float4*)&Qs[row * 56 + seg * 8] =
            *(const float4*)&g_Q[(((b << 12) + n0 + row) << 5) + seg * 8];
    }

    const uint32_t kOff = (L & 7) * 112 + ((L >> 3) & 3) * 16;
    const uint32_t vOff = ((((L >> 3) & 1) * 8 + (L & 7)) * 144) + (L >> 4) * 16;
    const uint32_t vOnes = ((((L >> 3) & 1) * 8 + (L & 7)) * 144) + 128;
    const uint32_t qRow = ((L >> 3) & 1) * 8 + (L & 7);
    const uint32_t qA0 = qsB + (m0w + qRow) * 112 + (L >> 4) * 16;
    const uint32_t qA1 = qsB + (m0w + 16 + qRow) * 112 + (L >> 4) * 16;

    uint32_t qf0[2][4], qf1[2][4];
    float o0[8][4], o1[8][4], l0[4], l1[4];
#pragma unroll
    for (int i = 0; i < 8; i++)
#pragma unroll
        for (int j = 0; j < 4; j++) { o0[i][j] = 0.f; o1[i][j] = 0.f; }
#pragma unroll
    for (int j = 0; j < 4; j++) { l0[j] = 0.f; l1[j] = 0.f; }

    for (int mt = 0; mt < 32; mt++) {
        const int buf = mt % 3;
        if (mt < 31) asm volatile("cp.async.wait_group 1;");
        else         asm volatile("cp.async.wait_group 0;");
        __syncthreads();    // tile mt visible; compute mt-1 done by all warps

        if (mt == 0) {      // Qs now visible
            ldsm4(qf0[0], qA0); ldsm4(qf0[1], qA0 + 32);
            ldsm4(qf1[0], qA1); ldsm4(qf1[1], qA1 + 32);
        }
        if (mt < 30) {      // prefetch tile mt+2 into buffer (mt+2)%3 (free now)
            const int it = mt + 2, ob = it % 3, r0g = it << 7;
            for (int u = tid; u < 512; u += 128) {
                int row = u >> 2, seg = u & 3;
                cpasync16(ksB + ob * K_BUF + row * 112 + seg * 16,
                          &g_K[(((b << 12) + r0g + row) << 5) + seg * 8]);
            }
            for (int u = tid; u < 1024; u += 128) {
                int vr = u >> 3, vs = u & 7;
                cpasync16(vsB + ob * V_BUF + vr * 144 + vs * 16,
                          &g_V[(((b << 12) + r0g + vr) << 6) + vs * 8]);
            }
            asm volatile("cp.async.commit_group;");
        }

#pragma unroll
        for (int half = 0; half < 2; half++) {
            const uint32_t kb = ksB + buf * K_BUF + half * 7168 + kOff;
            const uint32_t vb = vsB + buf * V_BUF + half * 9216 + vOff;
            const uint32_t vb1 = vsB + buf * V_BUF + half * 9216 + vOnes;

#pragma unroll
            for (int kc = 0; kc < 4; kc++) {
                uint32_t a0[4], a1[4];
#pragma unroll
                for (int j = 0; j < 4; j++) { a0[j] = SHIFT2; a1[j] = SHIFT2; }
                uint32_t kfa[4], kfb[4];
                ldsm4(kfa, kb + (2 * kc) * 896);
                ldsm4(kfb, kb + (2 * kc + 1) * 896);
                mmah(a0 + 0, qf0[0], kfa[0], kfa[1]);
                mmah(a0 + 0, qf0[1], kfa[2], kfa[3]);
                mmah(a0 + 2, qf0[0], kfb[0], kfb[1]);
                mmah(a0 + 2, qf0[1], kfb[2], kfb[3]);
                mmah(a1 + 0, qf1[0], kfa[0], kfa[1]);
                mmah(a1 + 0, qf1[1], kfa[2], kfa[3]);
                mmah(a1 + 2, qf1[0], kfb[0], kfb[1]);
                mmah(a1 + 2, qf1[1], kfb[2], kfb[3]);

#pragma unroll
                for (int j = 0; j < 4; j++) {
                    a0[j] = ex2h2(a0[j]);
                    a1[j] = ex2h2(a1[j]);
                }

#pragma unroll
                for (int cp = 0; cp < 4; cp++) {
                    uint32_t vf[4];
                    ldsm4t(vf, vb + kc * 2304 + cp * 32);
                    mmaf(o0[2 * cp],     a0, vf[0], vf[1]);
                    mmaf(o0[2 * cp + 1], a0, vf[2], vf[3]);
                    mmaf(o1[2 * cp],     a1, vf[0], vf[1]);
                    mmaf(o1[2 * cp + 1], a1, vf[2], vf[3]);
                }
                uint32_t of[2];
                ldsm2t(of, vb1 + kc * 2304);
                mmaf(l0, a0, of[0], of[1]);
                mmaf(l1, a1, of[0], of[1]);
            }
        }
    }
    __syncthreads();   // all compute done before zs/wzs overlay K buffers

    const float lr00 = __shfl_sync(0xffffffffu, l0[0], L & 28);
    const float lr01 = __shfl_sync(0xffffffffu, l0[2], L & 28);
    const float lr10 = __shfl_sync(0xffffffffu, l1[0], L & 28);
    const float lr11 = __shfl_sync(0xffffffffu, l1[2], L & 28);

    // ---- epilogue: z -> smem, wz GEMM (f32x2), + bz + h ----
    const float i00 = 1.f / lr00, i01 = 1.f / lr01;
    const float i10 = 1.f / lr10, i11 = 1.f / lr11;
#pragma unroll
    for (int nt = 0; nt < 8; nt++) {
        zs[(m0w + g) * 66 + 8 * nt + 2 * tig]          = o0[nt][0] * i00;
        zs[(m0w + g) * 66 + 8 * nt + 2 * tig + 1]      = o0[nt][1] * i00;
        zs[(m0w + g + 8) * 66 + 8 * nt + 2 * tig]      = o0[nt][2] * i01;
        zs[(m0w + g + 8) * 66 + 8 * nt + 2 * tig + 1]  = o0[nt][3] * i01;
        zs[(m0w + 16 + g) * 66 + 8 * nt + 2 * tig]     = o1[nt][0] * i10;
        zs[(m0w + 16 + g) * 66 + 8 * nt + 2 * tig + 1] = o1[nt][1] * i10;
        zs[(m0w + 24 + g) * 66 + 8 * nt + 2 * tig]     = o1[nt][2] * i11;
        zs[(m0w + 24 + g) * 66 + 8 * nt + 2 * tig + 1] = o1[nt][3] * i11;
    }
    for (int t = tid; t < CC * CC; t += 128) {
        int o = t >> 6, c = t & 63;
        wzs[c * 68 + o] = wz[t];
    }
    __syncthreads();

    unsigned long long acc2[32];
#pragma unroll
    for (int p = 0; p < 32; p++) acc2[p] = pk2(bz[2 * p], bz[2 * p + 1]);
#pragma unroll 4
    for (int c = 0; c < CC; c++) {
        float zv = zs[tid * 66 + c];
        unsigned long long zz = pk2(zv, zv);
        const ulonglong2* w2 = (const ulonglong2*)&wzs[c * 68];
#pragma unroll
        for (int p2 = 0; p2 < 16; p2++) {
            ulonglong2 ww = w2[p2];
            acc2[2 * p2]     = fma2(ww.x, zz, acc2[2 * p2]);
            acc2[2 * p2 + 1] = fma2(ww.y, zz, acc2[2 * p2 + 1]);
        }
    }
#pragma unroll
    for (int p = 0; p < 32; p++) {
        float lo, hi;
        upk2(lo, hi, acc2[p]);
        int g0 = (((b << 6) + 2 * p) << 12) + n0 + tid;
        int g1 = (((b << 6) + 2 * p + 1) << 12) + n0 + tid;
        outp[g0] = lo + hin[g0];
        outp[g1] = hi + hin[g1];
    }
}

// ---------------------------------------------------------------------------
extern "C" void kernel_launch(void* const* d_in, const int* in_sizes, int n_in,
                              void* d_out, int out_size)
{
    const float* h  = (const float*)d_in[0];
    const float* wq = (const float*)d_in[1];
    const float* bq = (const float*)d_in[2];
    const float* wk = (const float*)d_in[3];
    const float* bk = (const float*)d_in[4];
    const float* wv = (const float*)d_in[5];
    const float* bv = (const float*)d_in[6];
    const float* wz = (const float*)d_in[7];
    const float* bz = (const float*)d_in[8];
    float* out = (float*)d_out;

    cudaFuncSetAttribute(proj_kernel, cudaFuncAttributeMaxDynamicSharedMemorySize, PROJ_SMEM);
    proj_kernel<<<NB * 32, 256, PROJ_SMEM>>>(h, wq, bq, wk, bk, wv, bv);

    cudaFuncSetAttribute(attn_kernel, cudaFuncAttributeMaxDynamicSharedMemorySize, SMEM_ATTN);
    attn_kernel<<<NB * 32, 128, SMEM_ATTN>>>(wz, bz, h, out);
}

// round 15
// speedup vs baseline: 1.1046x; 1.1046x over previous
#include <cuda_runtime.h>
#include <cuda_fp16.h>
#include <cstdint>

#define NB 8
#define CC 64
#define DH 32
#define NN 4096
#define LOG2E 1.4426950408889634f

// fp16 staging buffers (device globals; no allocation allowed)
__device__ __half g_Q[NB * NN * DH];   // [B][N][32]
__device__ __half g_K[NB * NN * DH];   // [B][N][32] (pre-scaled by log2e)
__device__ __half g_V[NB * NN * CC];   // [B][N][64]

// ---------------------------------------------------------------------------
static __device__ __forceinline__ uint32_t cvta_s(const void* p) {
    return (uint32_t)__cvta_generic_to_shared(p);
}
static __device__ __forceinline__ uint32_t packh(float lo, float hi) {
    uint32_t r;
    asm("cvt.rn.f16x2.f32 %0, %1, %2;" : "=r"(r) : "f"(hi), "f"(lo));
    return r;
}
static __device__ __forceinline__ uint32_t ex2h2(uint32_t x) {
    uint32_t r;
    asm("ex2.approx.f16x2 %0, %1;" : "=r"(r) : "r"(x));
    return r;
}
static __device__ __forceinline__ void ldsm4(uint32_t* r, uint32_t a) {
    asm volatile("ldmatrix.sync.aligned.m8n8.x4.shared.b16 {%0,%1,%2,%3},[%4];"
        : "=r"(r[0]), "=r"(r[1]), "=r"(r[2]), "=r"(r[3]) : "r"(a));
}
static __device__ __forceinline__ void ldsm4t(uint32_t* r, uint32_t a) {
    asm volatile("ldmatrix.sync.aligned.m8n8.x4.trans.shared.b16 {%0,%1,%2,%3},[%4];"
        : "=r"(r[0]), "=r"(r[1]), "=r"(r[2]), "=r"(r[3]) : "r"(a));
}
static __device__ __forceinline__ void ldsm2t(uint32_t* r, uint32_t a) {
    asm volatile("ldmatrix.sync.aligned.m8n8.x2.trans.shared.b16 {%0,%1},[%2];"
        : "=r"(r[0]), "=r"(r[1]) : "r"(a));
}
// f16 x f16 -> f16 accum
static __device__ __forceinline__ void mmah(uint32_t* d, const uint32_t* a,
                                            uint32_t b0, uint32_t b1) {
    asm volatile("mma.sync.aligned.m16n8k16.row.col.f16.f16.f16.f16 "
        "{%0,%1},{%2,%3,%4,%5},{%6,%7},{%0,%1};"
        : "+r"(d[0]), "+r"(d[1])
        : "r"(a[0]), "r"(a[1]), "r"(a[2]), "r"(a[3]), "r"(b0), "r"(b1));
}
// f16 x f16 -> f32 accum
static __device__ __forceinline__ void mmaf(float* d, const uint32_t* a,
                                            uint32_t b0, uint32_t b1) {
    asm volatile("mma.sync.aligned.m16n8k16.row.col.f32.f16.f16.f32 "
        "{%0,%1,%2,%3},{%4,%5,%6,%7},{%8,%9},{%0,%1,%2,%3};"
        : "+f"(d[0]), "+f"(d[1]), "+f"(d[2]), "+f"(d[3])
        : "r"(a[0]), "r"(a[1]), "r"(a[2]), "r"(a[3]), "r"(b0), "r"(b1));
}
static __device__ __forceinline__ void cpasync16(uint32_t dst, const void* src) {
    asm volatile("cp.async.cg.shared.global [%0],[%1],16;" :: "r"(dst), "l"(src));
}

// ---------------------------------------------------------------------------
// Projection on tensor cores — 256 threads, 8 warps x 16 n-rows (R13).
// ---------------------------------------------------------------------------
#define WS_OFF 0        // W f16 [128][72]   (18432 B)
#define XS_OFF 18432    // x f16 [64][136]   (17408 B)
#define SB_OFF 35840    // bias f32 [128]    (512 B)
#define OS_OFF 36352    // out f16 [128][136] (34816 B)
#define PROJ_SMEM 71168

__global__ __launch_bounds__(256) void proj_kernel(
    const float* __restrict__ x,
    const float* __restrict__ wq, const float* __restrict__ bq,
    const float* __restrict__ wk, const float* __restrict__ bk,
    const float* __restrict__ wv, const float* __restrict__ bv)
{
    extern __shared__ char psm[];
    const uint32_t smB = cvta_s(psm);
    const int tid = threadIdx.x;
    const int wid = tid >> 5, L = tid & 31;
    const int g = L >> 2, tig = L & 3;
    const int b  = blockIdx.x >> 5;
    const int n0 = (blockIdx.x & 31) << 7;

    float* sb = (float*)(psm + SB_OFF);
    if (tid < 128) {
        float v = (tid < 32) ? bq[tid]
                : (tid < 64) ? bk[tid - 32] * LOG2E
                             : bv[tid - 64];
        sb[tid] = v;
    }
    for (int u = tid; u < 2048; u += 256) {
        int dim = u >> 4, c = (u & 15) << 2;
        float4 w;
        if (dim < 32)      w = *(const float4*)&wq[(dim << 6) + c];
        else if (dim < 64) {
            w = *(const float4*)&wk[((dim - 32) << 6) + c];
            w.x *= LOG2E; w.y *= LOG2E; w.z *= LOG2E; w.w *= LOG2E;
        } else             w = *(const float4*)&wv[((dim - 64) << 6) + c];
        *(uint2*)(psm + WS_OFF + dim * 144 + c * 2) =
            make_uint2(packh(w.x, w.y), packh(w.z, w.w));
    }
    for (int u = tid; u < 2048; u += 256) {
        int c = u >> 5, sg = u & 31;
        float4 xa = *(const float4*)&x[((((b << 6) + c) << 12)) + n0 + (sg << 2)];
        *(uint2*)(psm + XS_OFF + c * 272 + sg * 8) =
            make_uint2(packh(xa.x, xa.y), packh(xa.z, xa.w));
    }
    __syncthreads();

    const int mbase = wid << 4;
    uint32_t af[4][4];
    const uint32_t aRow = (L & 7) + ((L >> 4) << 3);
    const uint32_t aCol = ((L >> 3) & 1) << 4;
#pragma unroll
    for (int ks = 0; ks < 4; ks++)
        ldsm4t(af[ks], smB + XS_OFF + (ks * 16 + aRow) * 272 + mbase * 2 + aCol);

    const uint32_t wRow = L & 7;
    const uint32_t wCol = ((L >> 3) & 3) << 4;
#pragma unroll
    for (int nt = 0; nt < 16; nt++) {
        float d[4];
        float2 bias = *(float2*)&sb[nt * 8 + 2 * tig];
        d[0] = bias.x; d[1] = bias.y; d[2] = bias.x; d[3] = bias.y;
        uint32_t w0[4], w1[4];
        ldsm4(w0, smB + WS_OFF + (nt * 8 + wRow) * 144 + wCol);
        ldsm4(w1, smB + WS_OFF + (nt * 8 + wRow) * 144 + 64 + wCol);
        mmaf(d, af[0], w0[0], w0[1]);
        mmaf(d, af[1], w0[2], w0[3]);
        mmaf(d, af[2], w1[0], w1[1]);
        mmaf(d, af[3], w1[2], w1[3]);
        *(uint32_t*)(psm + OS_OFF + (mbase + g) * 272 + nt * 16 + tig * 4)
            = packh(d[0], d[1]);
        *(uint32_t*)(psm + OS_OFF + (mbase + g + 8) * 272 + nt * 16 + tig * 4)
            = packh(d[2], d[3]);
    }
    __syncthreads();

    for (int u = tid; u < 2048; u += 256) {
        int n = u >> 4, seg = u & 15;
        uint4 v = *(uint4*)(psm + OS_OFF + n * 272 + seg * 16);
        int gn = (b << 12) + n0 + n;
        if (seg < 4)      *(uint4*)&g_Q[(gn << 5) + seg * 8] = v;
        else if (seg < 8) *(uint4*)&g_K[(gn << 5) + (seg - 4) * 8] = v;
        else              *(uint4*)&g_V[(gn << 6) + (seg - 8) * 8] = v;
    }
}

// ---------------------------------------------------------------------------
// Flash attention: R13 main loop (2-buffer, f16-accum S w/ C-init -8,
// ex2.f16x2, PV f32, ones-column row sums) + NEW tensor-core wz epilogue.
// ---------------------------------------------------------------------------
#define QS_OFF  0
#define KS_OFF  14336
#define VS_OFF  43008
#define K_BUF   14336
#define V_BUF   18432
#define SMEM_ATTN 79872
#define SHIFT2  0xC800C800u     // f16x2 {-8, -8}

__global__ __launch_bounds__(128, 2) void attn_kernel(
    const float* __restrict__ wz, const float* __restrict__ bz,
    const float* __restrict__ hin, float* __restrict__ outp)
{
    extern __shared__ char sm8[];
    __half* Qs = (__half*)(sm8 + QS_OFF);

    const int tid = threadIdx.x;
    const int wid = tid >> 5, L = tid & 31;
    const int g = L >> 2, tig = L & 3;
    const int b  = blockIdx.x >> 5;
    const int n0 = (blockIdx.x & 31) << 7;
    const int m0w = wid << 5;

    const uint32_t smB = cvta_s(sm8);
    const uint32_t qsB = smB + QS_OFF;
    const uint32_t ksB = smB + KS_OFF;
    const uint32_t vsB = smB + VS_OFF;

    for (int t = tid; t < 256; t += 128) {
        int buf = t >> 7, row = t & 127;
        *(uint4*)(sm8 + VS_OFF + buf * V_BUF + row * 144 + 128) =
            make_uint4(0x00003C00u, 0u, 0u, 0u);
    }

    for (int u = tid; u < 512; u += 128) {
        int row = u >> 2, seg = u & 3;
        cpasync16(ksB + row * 112 + seg * 16,
                  &g_K[(((b << 12) + row) << 5) + seg * 8]);
    }
    for (int u = tid; u < 1024; u += 128) {
        int vr = u >> 3, vs = u & 7;
        cpasync16(vsB + vr * 144 + vs * 16,
                  &g_V[(((b << 12) + vr) << 6) + vs * 8]);
    }
    asm volatile("cp.async.commit_group;");
    for (int t = tid; t < 512; t += 128) {
        int row = t >> 2, seg = t & 3;
        *(float4*)&Qs[row * 56 + seg * 8] =
            *(const float4*)&g_Q[(((b << 12) + n0 + row) << 5) + seg * 8];
    }
    __syncthreads();

    const uint32_t kOff = (L & 7) * 112 + ((L >> 3) & 3) * 16;
    const uint32_t vOff = ((((L >> 3) & 1) * 8 + (L & 7)) * 144) + (L >> 4) * 16;
    const uint32_t vOnes = ((((L >> 3) & 1) * 8 + (L & 7)) * 144) + 128;
    const uint32_t qRow = ((L >> 3) & 1) * 8 + (L & 7);
    const uint32_t qA0 = qsB + (m0w + qRow) * 112 + (L >> 4) * 16;
    const uint32_t qA1 = qsB + (m0w + 16 + qRow) * 112 + (L >> 4) * 16;

    uint32_t qf0[2][4], qf1[2][4];
    ldsm4(qf0[0], qA0); ldsm4(qf0[1], qA0 + 32);
    ldsm4(qf1[0], qA1); ldsm4(qf1[1], qA1 + 32);

    float o0[8][4], o1[8][4], l0[4], l1[4];
#pragma unroll
    for (int i = 0; i < 8; i++)
#pragma unroll
        for (int j = 0; j < 4; j++) { o0[i][j] = 0.f; o1[i][j] = 0.f; }
#pragma unroll
    for (int j = 0; j < 4; j++) { l0[j] = 0.f; l1[j] = 0.f; }

    for (int mt = 0; mt < 32; mt++) {
        const int buf = mt & 1;
        if (mt < 31) {
            const int r0g = (mt + 1) << 7, ob = buf ^ 1;
            for (int u = tid; u < 512; u += 128) {
                int row = u >> 2, seg = u & 3;
                cpasync16(ksB + ob * K_BUF + row * 112 + seg * 16,
                          &g_K[(((b << 12) + r0g + row) << 5) + seg * 8]);
            }
            for (int u = tid; u < 1024; u += 128) {
                int vr = u >> 3, vs = u & 7;
                cpasync16(vsB + ob * V_BUF + vr * 144 + vs * 16,
                          &g_V[(((b << 12) + r0g + vr) << 6) + vs * 8]);
            }
            asm volatile("cp.async.commit_group;");
            asm volatile("cp.async.wait_group 1;");
        } else {
            asm volatile("cp.async.wait_group 0;");
        }
        __syncthreads();

#pragma unroll
        for (int half = 0; half < 2; half++) {
            const uint32_t kb = ksB + buf * K_BUF + half * 7168 + kOff;
            const uint32_t vb = vsB + buf * V_BUF + half * 9216 + vOff;
            const uint32_t vb1 = vsB + buf * V_BUF + half * 9216 + vOnes;

#pragma unroll
            for (int kc = 0; kc < 4; kc++) {
                uint32_t a0[4], a1[4];
#pragma unroll
                for (int j = 0; j < 4; j++) { a0[j] = SHIFT2; a1[j] = SHIFT2; }
                uint32_t kfa[4], kfb[4];
                ldsm4(kfa, kb + (2 * kc) * 896);
                ldsm4(kfb, kb + (2 * kc + 1) * 896);
                mmah(a0 + 0, qf0[0], kfa[0], kfa[1]);
                mmah(a0 + 0, qf0[1], kfa[2], kfa[3]);
                mmah(a0 + 2, qf0[0], kfb[0], kfb[1]);
                mmah(a0 + 2, qf0[1], kfb[2], kfb[3]);
                mmah(a1 + 0, qf1[0], kfa[0], kfa[1]);
                mmah(a1 + 0, qf1[1], kfa[2], kfa[3]);
                mmah(a1 + 2, qf1[0], kfb[0], kfb[1]);
                mmah(a1 + 2, qf1[1], kfb[2], kfb[3]);

#pragma unroll
                for (int j = 0; j < 4; j++) {
                    a0[j] = ex2h2(a0[j]);
                    a1[j] = ex2h2(a1[j]);
                }

#pragma unroll
                for (int cp = 0; cp < 4; cp++) {
                    uint32_t vf[4];
                    ldsm4t(vf, vb + kc * 2304 + cp * 32);
                    mmaf(o0[2 * cp],     a0, vf[0], vf[1]);
                    mmaf(o0[2 * cp + 1], a0, vf[2], vf[3]);
                    mmaf(o1[2 * cp],     a1, vf[0], vf[1]);
                    mmaf(o1[2 * cp + 1], a1, vf[2], vf[3]);
                }
                uint32_t of[2];
                ldsm2t(of, vb1 + kc * 2304);
                mmaf(l0, a0, of[0], of[1]);
                mmaf(l1, a1, of[0], of[1]);
            }
        }
        __syncthreads();
    }

    const float lr00 = __shfl_sync(0xffffffffu, l0[0], L & 28);
    const float lr01 = __shfl_sync(0xffffffffu, l0[2], L & 28);
    const float lr10 = __shfl_sync(0xffffffffu, l1[0], L & 28);
    const float lr11 = __shfl_sync(0xffffffffu, l1[2], L & 28);

    // ---- epilogue on tensor cores: z f16 [n][c], wz f16 [o][c] ----
    // zs16: 128 rows x 144 B (72 f16) at sm8+0; ws16: 64 rows x 144 B at +18432
    const uint32_t zsB = smB;
    const uint32_t wsB = smB + 18432;
    const float i00 = 1.f / lr00, i01 = 1.f / lr01;
    const float i10 = 1.f / lr10, i11 = 1.f / lr11;
#pragma unroll
    for (int nt = 0; nt < 8; nt++) {
        const uint32_t cOff = (8 * nt + 2 * tig) * 2;
        *(uint32_t*)(sm8 + (m0w + g) * 144 + cOff)      = packh(o0[nt][0] * i00, o0[nt][1] * i00);
        *(uint32_t*)(sm8 + (m0w + g + 8) * 144 + cOff)  = packh(o0[nt][2] * i01, o0[nt][3] * i01);
        *(uint32_t*)(sm8 + (m0w + g + 16) * 144 + cOff) = packh(o1[nt][0] * i10, o1[nt][1] * i10);
        *(uint32_t*)(sm8 + (m0w + g + 24) * 144 + cOff) = packh(o1[nt][2] * i11, o1[nt][3] * i11);
    }
    for (int u = tid; u < 2048; u += 128) {
        int o = u >> 5, c2 = u & 31;
        float2 w = *(const float2*)&wz[(o << 6) + 2 * c2];
        *(uint32_t*)(sm8 + 18432 + o * 144 + c2 * 4) = packh(w.x, w.y);
    }
    __syncthreads();

    // A fragments: z rows (Q-pattern), 2 m-chunks x 4 k16-steps
    uint32_t af[2][4];
    uint32_t af1[2][4];
    {
        const uint32_t zA0 = zsB + (m0w + qRow) * 144 + (L >> 4) * 16;
        const uint32_t zA1 = zsB + (m0w + 16 + qRow) * 144 + (L >> 4) * 16;
        ldsm4(af[0],  zA0);      ldsm4(af[1],  zA0 + 32);   // k0-31
        ldsm4(af1[0], zA1);      ldsm4(af1[1], zA1 + 32);
    }
    uint32_t af2[2][4], af3[2][4];
    {
        const uint32_t zA0 = zsB + (m0w + qRow) * 144 + (L >> 4) * 16;
        const uint32_t zA1 = zsB + (m0w + 16 + qRow) * 144 + (L >> 4) * 16;
        ldsm4(af2[0], zA0 + 64); ldsm4(af2[1], zA0 + 96);   // k32-63
        ldsm4(af3[0], zA1 + 64); ldsm4(af3[1], zA1 + 96);
    }

    const uint32_t wRow = (L & 7);
    const uint32_t wCol = ((L >> 3) & 3) * 16;
#pragma unroll
    for (int ot = 0; ot < 8; ot++) {
        uint32_t wf0[4], wf1[4];
        ldsm4(wf0, wsB + (ot * 8 + wRow) * 144 + wCol);        // c 0-31
        ldsm4(wf1, wsB + (ot * 8 + wRow) * 144 + 64 + wCol);   // c 32-63
        float2 bias = *(const float2*)&bz[ot * 8 + 2 * tig];
#pragma unroll
        for (int mc = 0; mc < 2; mc++) {
            float d[4];
            d[0] = bias.x; d[1] = bias.y; d[2] = bias.x; d[3] = bias.y;
            if (mc == 0) {
                mmaf(d, af[0],  wf0[0], wf0[1]);
                mmaf(d, af[1],  wf0[2], wf0[3]);
                mmaf(d, af2[0], wf1[0], wf1[1]);
                mmaf(d, af2[1], wf1[2], wf1[3]);
            } else {
                mmaf(d, af1[0], wf0[0], wf0[1]);
                mmaf(d, af1[1], wf0[2], wf0[3]);
                mmaf(d, af3[0], wf1[0], wf1[1]);
                mmaf(d, af3[1], wf1[2], wf1[3]);
            }
            const int nr = n0 + m0w + mc * 16 + g;
            const int oc = ot * 8 + 2 * tig;
            const int gi0 = (((b << 6) + oc) << 12) + nr;
            const int gi1 = gi0 + 4096;          // o+1
            outp[gi0]     = d[0] + hin[gi0];
            outp[gi1]     = d[1] + hin[gi1];
            outp[gi0 + 8] = d[2] + hin[gi0 + 8]; // row +8
            outp[gi1 + 8] = d[3] + hin[gi1 + 8];
        }
    }
}

// ---------------------------------------------------------------------------
extern "C" void kernel_launch(void* const* d_in, const int* in_sizes, int n_in,
                              void* d_out, int out_size)
{
    const float* h  = (const float*)d_in[0];
    const float* wq = (const float*)d_in[1];
    const float* bq = (const float*)d_in[2];
    const float* wk = (const float*)d_in[3];
    const float* bk = (const float*)d_in[4];
    const float* wv = (const float*)d_in[5];
    const float* bv = (const float*)d_in[6];
    const float* wz = (const float*)d_in[7];
    const float* bz = (const float*)d_in[8];
    float* out = (float*)d_out;

    cudaFuncSetAttribute(proj_kernel, cudaFuncAttributeMaxDynamicSharedMemorySize, PROJ_SMEM);
    proj_kernel<<<NB * 32, 256, PROJ_SMEM>>>(h, wq, bq, wk, bk, wv, bv);

    cudaFuncSetAttribute(attn_kernel, cudaFuncAttributeMaxDynamicSharedMemorySize, SMEM_ATTN);
    attn_kernel<<<NB * 32, 128, SMEM_ATTN>>>(wz, bz, h, out);
}